// round 15
// baseline (speedup 1.0000x reference)
#include <cuda_runtime.h>
#include <cuda_fp16.h>
#include <cstdint>

#define MAXN 100000
#define MAXE 1600000
#define F 128

// ---------------- scratch (static device globals; no allocs allowed) ----------
__device__ int    g_cnt[MAXN];
__device__ int    g_off[MAXN + 1];
__device__ int    g_rank[MAXE];                // per-edge rank within dst bucket
__device__ int    g_csr[MAXE];
__device__ unsigned long long g_tstat[512];    // decoupled-lookback status (flag<<32 | value)
__device__ unsigned g_tctr;                    // dynamic tile counter
__device__ __half g_xh[(size_t)MAXN * F];      // fp16 copy of x
__device__ __half g_hh[(size_t)MAXN * F];      // fp16 layer-1 activations
__device__ __half g_meanh[(size_t)MAXN * F];   // fp16 aggregated means
__device__ __half g_wth[2][128 * 256];         // per-layer [n][k] = fp16(concat(Wl,Wr)[k][n])

// ---------------- helpers ----------------------------------------------------
__device__ __forceinline__ void mma_f16(float* c, const uint32_t* a, const uint32_t* b) {
    asm volatile(
        "mma.sync.aligned.m16n8k16.row.col.f32.f16.f16.f32 "
        "{%0,%1,%2,%3}, {%4,%5,%6,%7}, {%8,%9}, {%0,%1,%2,%3};"
        : "+f"(c[0]), "+f"(c[1]), "+f"(c[2]), "+f"(c[3])
        : "r"(a[0]), "r"(a[1]), "r"(a[2]), "r"(a[3]), "r"(b[0]), "r"(b[1]));
}
__device__ __forceinline__ void ldsm4(uint32_t* r, uint32_t addr) {
    asm volatile("ldmatrix.sync.aligned.m8n8.x4.shared.b16 {%0,%1,%2,%3}, [%4];"
                 : "=r"(r[0]), "=r"(r[1]), "=r"(r[2]), "=r"(r[3]) : "r"(addr));
}
__device__ __forceinline__ uint32_t saddr(const void* p) {
    return (uint32_t)__cvta_generic_to_shared(p);
}
__device__ __forceinline__ void cp16(uint32_t dst, const void* src, int src_bytes) {
    asm volatile("cp.async.ca.shared.global [%0], [%1], 16, %2;"
                 :: "r"(dst), "l"(src), "r"(src_bytes) : "memory");
}
__device__ __forceinline__ void cp_commit() {
    asm volatile("cp.async.commit_group;" ::: "memory");
}
__device__ __forceinline__ void cp_wait0() {
    asm volatile("cp.async.wait_group 0;" ::: "memory");
}

// ---------------- CSR build --------------------------------------------------
__global__ void k_zero(int n4) {
    int i = blockIdx.x * 256 + threadIdx.x;       // int4 slots
    if (i * 4 < n4) {
        int4 z = make_int4(0, 0, 0, 0);
        *(int4*)&g_cnt[i * 4] = z;
    }
    if (i < 512) g_tstat[i] = 0ull;
    if (i == 0) g_tctr = 0u;
}

// histogram, 4 edges/thread; atomic return value = per-bucket rank
__global__ void k_hist(const int* __restrict__ dst, int E, int n) {
    int e = (blockIdx.x * 256 + threadIdx.x) * 4;
    if (e + 4 <= E) {
        int4 d = *(const int4*)(dst + e);
        int4 r = make_int4(0, 0, 0, 0);
        if ((unsigned)d.x < (unsigned)n) r.x = atomicAdd(&g_cnt[d.x], 1);
        if ((unsigned)d.y < (unsigned)n) r.y = atomicAdd(&g_cnt[d.y], 1);
        if ((unsigned)d.z < (unsigned)n) r.z = atomicAdd(&g_cnt[d.z], 1);
        if ((unsigned)d.w < (unsigned)n) r.w = atomicAdd(&g_cnt[d.w], 1);
        *(int4*)(g_rank + e) = r;
    } else {
        for (; e < E; e++) {
            int d = dst[e];
            int r = 0;
            if ((unsigned)d < (unsigned)n) r = atomicAdd(&g_cnt[d], 1);
            g_rank[e] = r;
        }
    }
}

// single-pass scan with decoupled lookback: g_cnt -> exclusive g_off (+ g_off[n])
__global__ void k_scan(int n) {
    __shared__ int sh[256];
    __shared__ int s_tile;
    __shared__ int s_excl;
    int t = threadIdx.x;
    if (t == 0) s_tile = (int)atomicAdd(&g_tctr, 1u);
    __syncthreads();
    int b = s_tile;
    int i = b * 256 + t;
    int c = (i < n) ? g_cnt[i] : 0;
    sh[t] = c;
    __syncthreads();
    for (int d = 1; d < 256; d <<= 1) {
        int u = (t >= d) ? sh[t - d] : 0;
        __syncthreads();
        sh[t] += u;
        __syncthreads();
    }
    int total = sh[255];
    if (t == 0) {
        if (b == 0) {
            atomicExch(&g_tstat[0], (2ull << 32) | (unsigned)total);
            s_excl = 0;
        } else {
            atomicExch(&g_tstat[b], (1ull << 32) | (unsigned)total);
            int excl = 0;
            int p = b - 1;
            while (true) {
                unsigned long long v = atomicAdd(&g_tstat[p], 0ull);
                unsigned f = (unsigned)(v >> 32);
                if (f == 2u) { excl += (int)(unsigned)v; break; }
                if (f == 1u) { excl += (int)(unsigned)v; p--; }
            }
            s_excl = excl;
            atomicExch(&g_tstat[b], (2ull << 32) | (unsigned)(excl + total));
        }
    }
    __syncthreads();
    int excl = s_excl;
    if (i < n) g_off[i] = excl + sh[t] - c;
    if (i == n - 1) g_off[n] = excl + sh[t];
}

// atomic-free scatter, 4 edges/thread: position = offset[dst] + rank
__global__ void k_scatter(const int* __restrict__ src,
                          const int* __restrict__ dst, int E, int n) {
    int e = (blockIdx.x * 256 + threadIdx.x) * 4;
    if (e + 4 <= E) {
        int4 d = *(const int4*)(dst + e);
        int4 s = *(const int4*)(src + e);
        int4 r = *(const int4*)(g_rank + e);
        int o0 = ((unsigned)d.x < (unsigned)n) ? g_off[d.x] : -1;
        int o1 = ((unsigned)d.y < (unsigned)n) ? g_off[d.y] : -1;
        int o2 = ((unsigned)d.z < (unsigned)n) ? g_off[d.z] : -1;
        int o3 = ((unsigned)d.w < (unsigned)n) ? g_off[d.w] : -1;
        if (o0 >= 0 && (unsigned)s.x < (unsigned)n) g_csr[o0 + r.x] = s.x;
        if (o1 >= 0 && (unsigned)s.y < (unsigned)n) g_csr[o1 + r.y] = s.y;
        if (o2 >= 0 && (unsigned)s.z < (unsigned)n) g_csr[o2 + r.z] = s.z;
        if (o3 >= 0 && (unsigned)s.w < (unsigned)n) g_csr[o3 + r.w] = s.w;
    } else {
        for (; e < E; e++) {
            int d = dst[e];
            int s = src[e];
            if ((unsigned)d < (unsigned)n && (unsigned)s < (unsigned)n)
                g_csr[g_off[d] + g_rank[e]] = s;
        }
    }
}

// ---------------- x -> fp16 (overlapped stream) -------------------------------
__global__ void k_x2h(const float* __restrict__ x, int n) {
    int i = blockIdx.x * 256 + threadIdx.x;
    if (i < n * 32) {
        float4 v = ((const float4*)x)[i];
        __half2 lo = __floats2half2_rn(v.x, v.y);
        __half2 hi = __floats2half2_rn(v.z, v.w);
        uint2 u;
        u.x = *(uint32_t*)&lo;
        u.y = *(uint32_t*)&hi;
        ((uint2*)g_xh)[i] = u;
    }
}

// ---------------- mean aggregation (CSR, fp16 gather, fp32 accumulate) -------
__global__ void k_agg(int use_gh, int n) {
    int node = blockIdx.x * 8 + (threadIdx.x >> 5);
    int lane = threadIdx.x & 31;
    if (node >= n) return;
    const __half* feat = use_gh ? g_hh : g_xh;
    int beg = g_off[node];
    int end = g_off[node + 1];
    const __half* base = feat + (size_t)lane * 4;

    float4 a0 = {0.f, 0.f, 0.f, 0.f}, a1 = a0, a2 = a0, a3 = a0;
    int e = beg;
    for (; e + 4 <= end; e += 4) {
        int s0 = __ldg(&g_csr[e + 0]);
        int s1 = __ldg(&g_csr[e + 1]);
        int s2 = __ldg(&g_csr[e + 2]);
        int s3 = __ldg(&g_csr[e + 3]);
        uint2 u0 = *(const uint2*)(base + (size_t)s0 * F);
        uint2 u1 = *(const uint2*)(base + (size_t)s1 * F);
        uint2 u2 = *(const uint2*)(base + (size_t)s2 * F);
        uint2 u3 = *(const uint2*)(base + (size_t)s3 * F);
        float2 p, q;
        p = __half22float2(*(__half2*)&u0.x); q = __half22float2(*(__half2*)&u0.y);
        a0.x += p.x; a0.y += p.y; a0.z += q.x; a0.w += q.y;
        p = __half22float2(*(__half2*)&u1.x); q = __half22float2(*(__half2*)&u1.y);
        a1.x += p.x; a1.y += p.y; a1.z += q.x; a1.w += q.y;
        p = __half22float2(*(__half2*)&u2.x); q = __half22float2(*(__half2*)&u2.y);
        a2.x += p.x; a2.y += p.y; a2.z += q.x; a2.w += q.y;
        p = __half22float2(*(__half2*)&u3.x); q = __half22float2(*(__half2*)&u3.y);
        a3.x += p.x; a3.y += p.y; a3.z += q.x; a3.w += q.y;
    }
    for (; e < end; e++) {
        int s0 = __ldg(&g_csr[e]);
        uint2 u0 = *(const uint2*)(base + (size_t)s0 * F);
        float2 p = __half22float2(*(__half2*)&u0.x);
        float2 q = __half22float2(*(__half2*)&u0.y);
        a0.x += p.x; a0.y += p.y; a0.z += q.x; a0.w += q.y;
    }
    a0.x += a1.x + a2.x + a3.x;
    a0.y += a1.y + a2.y + a3.y;
    a0.z += a1.z + a2.z + a3.z;
    a0.w += a1.w + a2.w + a3.w;

    int deg = end - beg;
    float inv = 1.0f / (float)max(deg, 1);
    __half2 lo = __floats2half2_rn(a0.x * inv, a0.y * inv);
    __half2 hi = __floats2half2_rn(a0.z * inv, a0.w * inv);
    uint2 u;
    u.x = *(uint32_t*)&lo;
    u.y = *(uint32_t*)&hi;
    *(uint2*)(g_meanh + (size_t)node * F + lane * 4) = u;
}

// ---------------- weight prep (both layers): g_wth[l][n][k] -------------------
__global__ void k_prep(const float* __restrict__ Wl1, const float* __restrict__ Wr1,
                       const float* __restrict__ Wl2, const float* __restrict__ Wr2) {
    int idx = blockIdx.x * 256 + threadIdx.x;   // 2*32768 total
    if (idx >= 2 * 128 * 256) return;
    int l  = idx >> 15;
    int nn = (idx >> 8) & 127;
    int k  = idx & 255;
    const float* Wl = l ? Wl2 : Wl1;
    const float* Wr = l ? Wr2 : Wr1;
    float v = (k < 128) ? Wl[k * 128 + nn] : Wr[(k - 128) * 128 + nn];
    g_wth[l][nn * 256 + k] = __float2half_rn(v);
}

// ---------------- fp16 mma.sync dual GEMM (ldmatrix + cp.async pipeline) -----
__global__ __launch_bounds__(256) void k_gemm_mma(
    const float* __restrict__ bias,
    float* __restrict__ out_g, int layer, int n)
{
    __shared__ uint32_t sA[2][128][20];   // 16 used + 4 pad (80B row stride)
    __shared__ uint32_t sB[2][128][20];
    __shared__ float sBias[128];

    const __half* selfp = layer ? g_hh : g_xh;
    const __half* wt = g_wth[layer];

    int t = threadIdx.x;
    int warp = t >> 5;
    int lane = t & 31;
    int warp_m = warp & 3;
    int warp_n = warp >> 2;
    int group = lane >> 2;
    int tig = lane & 3;
    int lrow = lane & 15;
    int lksel = lane >> 4;
    int row0 = blockIdx.x * 128;

    if (t < 128) sBias[t] = bias[t];

    int srow = t >> 2;
    int sc4 = t & 3;
    int r_g0 = row0 + srow;
    int r_g1 = row0 + srow + 64;

    auto stage = [&](int ch, int b) {
        const __half* srcp = (ch < 4) ? g_meanh : selfp;
        int kcol = (ch & 3) * 32 + sc4 * 8;
        int r0c = (r_g0 < n) ? r_g0 : 0;
        int r1c = (r_g1 < n) ? r_g1 : 0;
        cp16(saddr(&sA[b][srow][sc4 * 4]),
             srcp + (size_t)r0c * F + kcol, (r_g0 < n) ? 16 : 0);
        cp16(saddr(&sA[b][srow + 64][sc4 * 4]),
             srcp + (size_t)r1c * F + kcol, (r_g1 < n) ? 16 : 0);
        const __half* wsrc = wt + (ch & 7) * 32 + sc4 * 8;
        cp16(saddr(&sB[b][srow][sc4 * 4]), wsrc + srow * 256, 16);
        cp16(saddr(&sB[b][srow + 64][sc4 * 4]), wsrc + (srow + 64) * 256, 16);
        cp_commit();
    };

    float acc[2][8][4];
#pragma unroll
    for (int i = 0; i < 2; i++)
#pragma unroll
        for (int j = 0; j < 8; j++)
#pragma unroll
            for (int q = 0; q < 4; q++) acc[i][j][q] = 0.f;

    stage(0, 0);
    cp_wait0();
    __syncthreads();

#pragma unroll
    for (int ch = 0; ch < 8; ch++) {
        int buf = ch & 1;
        if (ch < 7) stage(ch + 1, buf ^ 1);

#pragma unroll
        for (int ks = 0; ks < 2; ks++) {
            uint32_t a[2][4];
#pragma unroll
            for (int mf = 0; mf < 2; mf++) {
                ldsm4(a[mf], saddr(&sA[buf][warp_m * 32 + mf * 16 + lrow]
                                      [ks * 8 + lksel * 4]));
            }
            uint32_t bf[8][2];
#pragma unroll
            for (int nfp = 0; nfp < 4; nfp++) {
                uint32_t r4[4];
                ldsm4(r4, saddr(&sB[buf][warp_n * 64 + nfp * 16 + lrow]
                                   [ks * 8 + lksel * 4]));
                bf[nfp * 2][0] = r4[0];
                bf[nfp * 2 + 1][0] = r4[1];
                bf[nfp * 2][1] = r4[2];
                bf[nfp * 2 + 1][1] = r4[3];
            }
#pragma unroll
            for (int mf = 0; mf < 2; mf++)
#pragma unroll
                for (int nf = 0; nf < 8; nf++)
                    mma_f16(acc[mf][nf], a[mf], bf[nf]);
        }

        if (ch < 7) {
            cp_wait0();
            __syncthreads();
        }
    }

    // epilogue
#pragma unroll
    for (int mf = 0; mf < 2; mf++) {
        int r_lo = row0 + warp_m * 32 + mf * 16 + group;
        int r_hi = r_lo + 8;
#pragma unroll
        for (int nf = 0; nf < 8; nf++) {
            int cc = warp_n * 64 + nf * 8 + tig * 2;
            float2 lo, hi;
            lo.x = acc[mf][nf][0] + sBias[cc];
            lo.y = acc[mf][nf][1] + sBias[cc + 1];
            hi.x = acc[mf][nf][2] + sBias[cc];
            hi.y = acc[mf][nf][3] + sBias[cc + 1];
            if (layer == 0) {
                lo.x = fmaxf(lo.x, 0.f); lo.y = fmaxf(lo.y, 0.f);
                hi.x = fmaxf(hi.x, 0.f); hi.y = fmaxf(hi.y, 0.f);
                __half2 l2 = __floats2half2_rn(lo.x, lo.y);
                __half2 h2 = __floats2half2_rn(hi.x, hi.y);
                if (r_lo < n) *(__half2*)&g_hh[(size_t)r_lo * F + cc] = l2;
                if (r_hi < n) *(__half2*)&g_hh[(size_t)r_hi * F + cc] = h2;
            } else {
                if (r_lo < n) *(float2*)&out_g[(size_t)r_lo * F + cc] = lo;
                if (r_hi < n) *(float2*)&out_g[(size_t)r_hi * F + cc] = hi;
            }
        }
    }
}

// ---------------- launch: kernel launches + capture-safe stream fork ----------
extern "C" void kernel_launch(void* const* d_in, const int* in_sizes, int n_in,
                              void* d_out, int out_size) {
    const float* x   = (const float*)d_in[0];
    const int*   ei  = (const int*)d_in[1];   // int32 [2, E]
    const float* Wl1 = (const float*)d_in[2];
    const float* Wr1 = (const float*)d_in[3];
    const float* b1  = (const float*)d_in[4];
    const float* Wl2 = (const float*)d_in[5];
    const float* Wr2 = (const float*)d_in[6];
    const float* b2  = (const float*)d_in[7];
    float* out = (float*)d_out;

    int n = in_sizes[0] / F;
    int E = in_sizes[1] / 2;
    if (n > MAXN) n = MAXN;
    if (E > MAXE) E = MAXE;

    const int* src = ei;
    const int* dst = ei + E;

    int nb = (n + 255) / 256;            // scan tiles
    int nq = (((n + 3) & ~3) + 1023) / 1024;
    int eq = (E + 1023) / 1024;          // 4-edge-per-thread blocks

    cudaStream_t s1;
    cudaStreamCreateWithFlags(&s1, cudaStreamNonBlocking);
    cudaEvent_t evFork, evJoin;
    cudaEventCreateWithFlags(&evFork, cudaEventDisableTiming);
    cudaEventCreateWithFlags(&evJoin, cudaEventDisableTiming);

    cudaEventRecord(evFork, 0);
    cudaStreamWaitEvent(s1, evFork, 0);

    // side stream: x->fp16 + weight prep (independent of CSR chain)
    k_x2h<<<(n * 32 + 255) / 256, 256, 0, s1>>>(x, n);
    k_prep<<<256, 256, 0, s1>>>(Wl1, Wr1, Wl2, Wr2);
    cudaEventRecord(evJoin, s1);

    // main stream: CSR build (single-pass scan)
    k_zero<<<nq < 2 ? 2 : nq, 256>>>((n + 3) & ~3);
    k_hist<<<eq, 256>>>(dst, E, n);
    k_scan<<<nb, 256>>>(n);
    k_scatter<<<eq, 256>>>(src, dst, E, n);

    // join: aggregation needs g_xh, GEMM needs g_wth
    cudaStreamWaitEvent(0, evJoin, 0);

    int agg_grid  = (n + 7) / 8;
    int gemm_grid = (n + 127) / 128;

    // layer 1 (serial — R14 overlap was a measured regression)
    k_agg<<<agg_grid, 256>>>(0, n);
    k_gemm_mma<<<gemm_grid, 256>>>(b1, nullptr, 0, n);

    // layer 2
    k_agg<<<agg_grid, 256>>>(1, n);
    k_gemm_mma<<<gemm_grid, 256>>>(b2, out, 1, n);

    cudaEventDestroy(evFork);
    cudaEventDestroy(evJoin);
    cudaStreamDestroy(s1);
}

// round 17
// speedup vs baseline: 1.3907x; 1.3907x over previous
#include <cuda_runtime.h>
#include <cuda_fp16.h>
#include <cstdint>

#define MAXN 100000
#define MAXE 1600000
#define F 128

// ---------------- scratch (static device globals; no allocs allowed) ----------
__device__ int    g_cnt[MAXN];
__device__ int    g_off[MAXN + 1];
__device__ int    g_rank[MAXE];                // per-edge rank within dst bucket
__device__ int    g_csr[MAXE];
__device__ int    g_blk[512];
__device__ int    g_blkoff[512];
__device__ __half g_xh[(size_t)MAXN * F];      // fp16 copy of x
__device__ __half g_hh[(size_t)MAXN * F];      // fp16 layer-1 activations
__device__ __half g_meanh[(size_t)MAXN * F];   // fp16 aggregated means
__device__ __half g_wth[2][128 * 256];         // per-layer [n][k] = fp16(concat(Wl,Wr)[k][n])

// ---------------- helpers ----------------------------------------------------
__device__ __forceinline__ void mma_f16(float* c, const uint32_t* a, const uint32_t* b) {
    asm volatile(
        "mma.sync.aligned.m16n8k16.row.col.f32.f16.f16.f32 "
        "{%0,%1,%2,%3}, {%4,%5,%6,%7}, {%8,%9}, {%0,%1,%2,%3};"
        : "+f"(c[0]), "+f"(c[1]), "+f"(c[2]), "+f"(c[3])
        : "r"(a[0]), "r"(a[1]), "r"(a[2]), "r"(a[3]), "r"(b[0]), "r"(b[1]));
}
__device__ __forceinline__ void ldsm4(uint32_t* r, uint32_t addr) {
    asm volatile("ldmatrix.sync.aligned.m8n8.x4.shared.b16 {%0,%1,%2,%3}, [%4];"
                 : "=r"(r[0]), "=r"(r[1]), "=r"(r[2]), "=r"(r[3]) : "r"(addr));
}
__device__ __forceinline__ uint32_t saddr(const void* p) {
    return (uint32_t)__cvta_generic_to_shared(p);
}
__device__ __forceinline__ void cp16(uint32_t dst, const void* src, int src_bytes) {
    asm volatile("cp.async.ca.shared.global [%0], [%1], 16, %2;"
                 :: "r"(dst), "l"(src), "r"(src_bytes) : "memory");
}
__device__ __forceinline__ void cp_commit() {
    asm volatile("cp.async.commit_group;" ::: "memory");
}
__device__ __forceinline__ void cp_wait0() {
    asm volatile("cp.async.wait_group 0;" ::: "memory");
}
__device__ __forceinline__ void acc8(float4& a, uint2 u) {
    float2 p = __half22float2(*(__half2*)&u.x);
    float2 q = __half22float2(*(__half2*)&u.y);
    a.x += p.x; a.y += p.y; a.z += q.x; a.w += q.y;
}

// ---------------- CSR build --------------------------------------------------
__global__ void k_zero(int n4) {
    int i = blockIdx.x * 256 + threadIdx.x;       // int4 slots
    if (i * 4 < n4) {
        int4 z = make_int4(0, 0, 0, 0);
        *(int4*)&g_cnt[i * 4] = z;
    }
}

// histogram, 4 edges/thread; atomic return value = per-bucket rank
__global__ void k_hist(const int* __restrict__ dst, int E, int n) {
    int e = (blockIdx.x * 256 + threadIdx.x) * 4;
    if (e + 4 <= E) {
        int4 d = *(const int4*)(dst + e);
        int4 r = make_int4(0, 0, 0, 0);
        if ((unsigned)d.x < (unsigned)n) r.x = atomicAdd(&g_cnt[d.x], 1);
        if ((unsigned)d.y < (unsigned)n) r.y = atomicAdd(&g_cnt[d.y], 1);
        if ((unsigned)d.z < (unsigned)n) r.z = atomicAdd(&g_cnt[d.z], 1);
        if ((unsigned)d.w < (unsigned)n) r.w = atomicAdd(&g_cnt[d.w], 1);
        *(int4*)(g_rank + e) = r;
    } else {
        for (; e < E; e++) {
            int d = dst[e];
            int r = 0;
            if ((unsigned)d < (unsigned)n) r = atomicAdd(&g_cnt[d], 1);
            g_rank[e] = r;
        }
    }
}

__global__ void k_blksum(int n) {
    __shared__ int sh[256];
    int b = blockIdx.x, t = threadIdx.x;
    int i = b * 256 + t;
    sh[t] = (i < n) ? g_cnt[i] : 0;
    __syncthreads();
    for (int s = 128; s > 0; s >>= 1) {
        if (t < s) sh[t] += sh[t + s];
        __syncthreads();
    }
    if (t == 0) g_blk[b] = sh[0];
}

__global__ void k_blkscan(int nb, int n) {
    __shared__ int sh[512];
    int t = threadIdx.x;
    int v = (t < nb) ? g_blk[t] : 0;
    sh[t] = v;
    __syncthreads();
    for (int d = 1; d < 512; d <<= 1) {
        int u = (t >= d) ? sh[t - d] : 0;
        __syncthreads();
        sh[t] += u;
        __syncthreads();
    }
    g_blkoff[t] = sh[t] - v;
    if (t == 511) g_off[n] = sh[511];
}

__global__ void k_scanout(int n) {
    __shared__ int sh[256];
    int b = blockIdx.x, t = threadIdx.x;
    int i = b * 256 + t;
    int c = (i < n) ? g_cnt[i] : 0;
    sh[t] = c;
    __syncthreads();
    for (int d = 1; d < 256; d <<= 1) {
        int u = (t >= d) ? sh[t - d] : 0;
        __syncthreads();
        sh[t] += u;
        __syncthreads();
    }
    if (i < n) g_off[i] = g_blkoff[b] + sh[t] - c;
}

// atomic-free scatter, 4 edges/thread: position = offset[dst] + rank
__global__ void k_scatter(const int* __restrict__ src,
                          const int* __restrict__ dst, int E, int n) {
    int e = (blockIdx.x * 256 + threadIdx.x) * 4;
    if (e + 4 <= E) {
        int4 d = *(const int4*)(dst + e);
        int4 s = *(const int4*)(src + e);
        int4 r = *(const int4*)(g_rank + e);
        int o0 = ((unsigned)d.x < (unsigned)n) ? g_off[d.x] : -1;
        int o1 = ((unsigned)d.y < (unsigned)n) ? g_off[d.y] : -1;
        int o2 = ((unsigned)d.z < (unsigned)n) ? g_off[d.z] : -1;
        int o3 = ((unsigned)d.w < (unsigned)n) ? g_off[d.w] : -1;
        if (o0 >= 0 && (unsigned)s.x < (unsigned)n) g_csr[o0 + r.x] = s.x;
        if (o1 >= 0 && (unsigned)s.y < (unsigned)n) g_csr[o1 + r.y] = s.y;
        if (o2 >= 0 && (unsigned)s.z < (unsigned)n) g_csr[o2 + r.z] = s.z;
        if (o3 >= 0 && (unsigned)s.w < (unsigned)n) g_csr[o3 + r.w] = s.w;
    } else {
        for (; e < E; e++) {
            int d = dst[e];
            int s = src[e];
            if ((unsigned)d < (unsigned)n && (unsigned)s < (unsigned)n)
                g_csr[g_off[d] + g_rank[e]] = s;
        }
    }
}

// ---------------- x -> fp16 (overlapped stream) -------------------------------
__global__ void k_x2h(const float* __restrict__ x, int n) {
    int i = blockIdx.x * 256 + threadIdx.x;
    if (i < n * 32) {
        float4 v = ((const float4*)x)[i];
        __half2 lo = __floats2half2_rn(v.x, v.y);
        __half2 hi = __floats2half2_rn(v.z, v.w);
        uint2 u;
        u.x = *(uint32_t*)&lo;
        u.y = *(uint32_t*)&hi;
        ((uint2*)g_xh)[i] = u;
    }
}

// ---------------- mean aggregation (CSR, fp16 gather, fp32 accumulate) -------
// 8 nodes per 256-thread block; 32 lanes per node; 8-edge unroll (MLP=8).
__global__ void k_agg(int use_gh, int n) {
    int node = blockIdx.x * 8 + (threadIdx.x >> 5);
    int lane = threadIdx.x & 31;
    if (node >= n) return;
    const __half* feat = use_gh ? g_hh : g_xh;
    int beg = g_off[node];
    int end = g_off[node + 1];
    const __half* base = feat + (size_t)lane * 4;

    float4 a0 = {0.f, 0.f, 0.f, 0.f}, a1 = a0, a2 = a0, a3 = a0;
    int e = beg;
    for (; e + 8 <= end; e += 8) {
        int s0 = __ldg(&g_csr[e + 0]);
        int s1 = __ldg(&g_csr[e + 1]);
        int s2 = __ldg(&g_csr[e + 2]);
        int s3 = __ldg(&g_csr[e + 3]);
        int s4 = __ldg(&g_csr[e + 4]);
        int s5 = __ldg(&g_csr[e + 5]);
        int s6 = __ldg(&g_csr[e + 6]);
        int s7 = __ldg(&g_csr[e + 7]);
        uint2 u0 = *(const uint2*)(base + (size_t)s0 * F);
        uint2 u1 = *(const uint2*)(base + (size_t)s1 * F);
        uint2 u2 = *(const uint2*)(base + (size_t)s2 * F);
        uint2 u3 = *(const uint2*)(base + (size_t)s3 * F);
        uint2 u4 = *(const uint2*)(base + (size_t)s4 * F);
        uint2 u5 = *(const uint2*)(base + (size_t)s5 * F);
        uint2 u6 = *(const uint2*)(base + (size_t)s6 * F);
        uint2 u7 = *(const uint2*)(base + (size_t)s7 * F);
        acc8(a0, u0); acc8(a1, u1); acc8(a2, u2); acc8(a3, u3);
        acc8(a0, u4); acc8(a1, u5); acc8(a2, u6); acc8(a3, u7);
    }
    for (; e + 4 <= end; e += 4) {
        int s0 = __ldg(&g_csr[e + 0]);
        int s1 = __ldg(&g_csr[e + 1]);
        int s2 = __ldg(&g_csr[e + 2]);
        int s3 = __ldg(&g_csr[e + 3]);
        uint2 u0 = *(const uint2*)(base + (size_t)s0 * F);
        uint2 u1 = *(const uint2*)(base + (size_t)s1 * F);
        uint2 u2 = *(const uint2*)(base + (size_t)s2 * F);
        uint2 u3 = *(const uint2*)(base + (size_t)s3 * F);
        acc8(a0, u0); acc8(a1, u1); acc8(a2, u2); acc8(a3, u3);
    }
    for (; e < end; e++) {
        int s0 = __ldg(&g_csr[e]);
        uint2 u0 = *(const uint2*)(base + (size_t)s0 * F);
        acc8(a0, u0);
    }
    a0.x += a1.x + a2.x + a3.x;
    a0.y += a1.y + a2.y + a3.y;
    a0.z += a1.z + a2.z + a3.z;
    a0.w += a1.w + a2.w + a3.w;

    int deg = end - beg;
    float inv = 1.0f / (float)max(deg, 1);
    __half2 lo = __floats2half2_rn(a0.x * inv, a0.y * inv);
    __half2 hi = __floats2half2_rn(a0.z * inv, a0.w * inv);
    uint2 u;
    u.x = *(uint32_t*)&lo;
    u.y = *(uint32_t*)&hi;
    *(uint2*)(g_meanh + (size_t)node * F + lane * 4) = u;
}

// ---------------- weight prep (both layers): g_wth[l][n][k] -------------------
__global__ void k_prep(const float* __restrict__ Wl1, const float* __restrict__ Wr1,
                       const float* __restrict__ Wl2, const float* __restrict__ Wr2) {
    int idx = blockIdx.x * 256 + threadIdx.x;   // 2*32768 total
    if (idx >= 2 * 128 * 256) return;
    int l  = idx >> 15;
    int nn = (idx >> 8) & 127;
    int k  = idx & 255;
    const float* Wl = l ? Wl2 : Wl1;
    const float* Wr = l ? Wr2 : Wr1;
    float v = (k < 128) ? Wl[k * 128 + nn] : Wr[(k - 128) * 128 + nn];
    g_wth[l][nn * 256 + k] = __float2half_rn(v);
}

// ---------------- fp16 mma.sync dual GEMM (ldmatrix + cp.async pipeline) -----
__global__ __launch_bounds__(256) void k_gemm_mma(
    const float* __restrict__ bias,
    float* __restrict__ out_g, int layer, int n)
{
    __shared__ uint32_t sA[2][128][20];   // 16 used + 4 pad (80B row stride)
    __shared__ uint32_t sB[2][128][20];
    __shared__ float sBias[128];

    const __half* selfp = layer ? g_hh : g_xh;
    const __half* wt = g_wth[layer];

    int t = threadIdx.x;
    int warp = t >> 5;
    int lane = t & 31;
    int warp_m = warp & 3;
    int warp_n = warp >> 2;
    int group = lane >> 2;
    int tig = lane & 3;
    int lrow = lane & 15;
    int lksel = lane >> 4;
    int row0 = blockIdx.x * 128;

    if (t < 128) sBias[t] = bias[t];

    int srow = t >> 2;
    int sc4 = t & 3;
    int r_g0 = row0 + srow;
    int r_g1 = row0 + srow + 64;

    auto stage = [&](int ch, int b) {
        const __half* srcp = (ch < 4) ? g_meanh : selfp;
        int kcol = (ch & 3) * 32 + sc4 * 8;
        int r0c = (r_g0 < n) ? r_g0 : 0;
        int r1c = (r_g1 < n) ? r_g1 : 0;
        cp16(saddr(&sA[b][srow][sc4 * 4]),
             srcp + (size_t)r0c * F + kcol, (r_g0 < n) ? 16 : 0);
        cp16(saddr(&sA[b][srow + 64][sc4 * 4]),
             srcp + (size_t)r1c * F + kcol, (r_g1 < n) ? 16 : 0);
        const __half* wsrc = wt + (ch & 7) * 32 + sc4 * 8;
        cp16(saddr(&sB[b][srow][sc4 * 4]), wsrc + srow * 256, 16);
        cp16(saddr(&sB[b][srow + 64][sc4 * 4]), wsrc + (srow + 64) * 256, 16);
        cp_commit();
    };

    float acc[2][8][4];
#pragma unroll
    for (int i = 0; i < 2; i++)
#pragma unroll
        for (int j = 0; j < 8; j++)
#pragma unroll
            for (int q = 0; q < 4; q++) acc[i][j][q] = 0.f;

    stage(0, 0);
    cp_wait0();
    __syncthreads();

#pragma unroll
    for (int ch = 0; ch < 8; ch++) {
        int buf = ch & 1;
        if (ch < 7) stage(ch + 1, buf ^ 1);

#pragma unroll
        for (int ks = 0; ks < 2; ks++) {
            uint32_t a[2][4];
#pragma unroll
            for (int mf = 0; mf < 2; mf++) {
                ldsm4(a[mf], saddr(&sA[buf][warp_m * 32 + mf * 16 + lrow]
                                      [ks * 8 + lksel * 4]));
            }
            uint32_t bf[8][2];
#pragma unroll
            for (int nfp = 0; nfp < 4; nfp++) {
                uint32_t r4[4];
                ldsm4(r4, saddr(&sB[buf][warp_n * 64 + nfp * 16 + lrow]
                                   [ks * 8 + lksel * 4]));
                bf[nfp * 2][0] = r4[0];
                bf[nfp * 2 + 1][0] = r4[1];
                bf[nfp * 2][1] = r4[2];
                bf[nfp * 2 + 1][1] = r4[3];
            }
#pragma unroll
            for (int mf = 0; mf < 2; mf++)
#pragma unroll
                for (int nf = 0; nf < 8; nf++)
                    mma_f16(acc[mf][nf], a[mf], bf[nf]);
        }

        if (ch < 7) {
            cp_wait0();
            __syncthreads();
        }
    }

    // epilogue
#pragma unroll
    for (int mf = 0; mf < 2; mf++) {
        int r_lo = row0 + warp_m * 32 + mf * 16 + group;
        int r_hi = r_lo + 8;
#pragma unroll
        for (int nf = 0; nf < 8; nf++) {
            int cc = warp_n * 64 + nf * 8 + tig * 2;
            float2 lo, hi;
            lo.x = acc[mf][nf][0] + sBias[cc];
            lo.y = acc[mf][nf][1] + sBias[cc + 1];
            hi.x = acc[mf][nf][2] + sBias[cc];
            hi.y = acc[mf][nf][3] + sBias[cc + 1];
            if (layer == 0) {
                lo.x = fmaxf(lo.x, 0.f); lo.y = fmaxf(lo.y, 0.f);
                hi.x = fmaxf(hi.x, 0.f); hi.y = fmaxf(hi.y, 0.f);
                __half2 l2 = __floats2half2_rn(lo.x, lo.y);
                __half2 h2 = __floats2half2_rn(hi.x, hi.y);
                if (r_lo < n) *(__half2*)&g_hh[(size_t)r_lo * F + cc] = l2;
                if (r_hi < n) *(__half2*)&g_hh[(size_t)r_hi * F + cc] = h2;
            } else {
                if (r_lo < n) __stcs((float2*)&out_g[(size_t)r_lo * F + cc], lo);
                if (r_hi < n) __stcs((float2*)&out_g[(size_t)r_hi * F + cc], hi);
            }
        }
    }
}

// ---------------- launch: kernel launches + capture-safe stream fork ----------
extern "C" void kernel_launch(void* const* d_in, const int* in_sizes, int n_in,
                              void* d_out, int out_size) {
    const float* x   = (const float*)d_in[0];
    const int*   ei  = (const int*)d_in[1];   // int32 [2, E]
    const float* Wl1 = (const float*)d_in[2];
    const float* Wr1 = (const float*)d_in[3];
    const float* b1  = (const float*)d_in[4];
    const float* Wl2 = (const float*)d_in[5];
    const float* Wr2 = (const float*)d_in[6];
    const float* b2  = (const float*)d_in[7];
    float* out = (float*)d_out;

    int n = in_sizes[0] / F;
    int E = in_sizes[1] / 2;
    if (n > MAXN) n = MAXN;
    if (E > MAXE) E = MAXE;

    const int* src = ei;
    const int* dst = ei + E;

    int nb = (n + 255) / 256;
    int nq = (((n + 3) & ~3) + 1023) / 1024;
    int eq = (E + 1023) / 1024;          // 4-edge-per-thread blocks

    cudaStream_t s1;
    cudaStreamCreateWithFlags(&s1, cudaStreamNonBlocking);
    cudaEvent_t evFork, evJoin;
    cudaEventCreateWithFlags(&evFork, cudaEventDisableTiming);
    cudaEventCreateWithFlags(&evJoin, cudaEventDisableTiming);

    cudaEventRecord(evFork, 0);
    cudaStreamWaitEvent(s1, evFork, 0);

    // side stream: x->fp16 + weight prep (independent of CSR chain)
    k_x2h<<<(n * 32 + 255) / 256, 256, 0, s1>>>(x, n);
    k_prep<<<256, 256, 0, s1>>>(Wl1, Wr1, Wl2, Wr2);
    cudaEventRecord(evJoin, s1);

    // main stream: CSR build (proven 3-kernel scan chain)
    k_zero<<<nq, 256>>>((n + 3) & ~3);
    k_hist<<<eq, 256>>>(dst, E, n);
    k_blksum<<<nb, 256>>>(n);
    k_blkscan<<<1, 512>>>(nb, n);
    k_scanout<<<nb, 256>>>(n);
    k_scatter<<<eq, 256>>>(src, dst, E, n);

    // join: aggregation needs g_xh, GEMM needs g_wth
    cudaStreamWaitEvent(0, evJoin, 0);

    int agg_grid  = (n + 7) / 8;
    int gemm_grid = (n + 127) / 128;

    // layer 1 (serial — overlap was a measured regression in R14)
    k_agg<<<agg_grid, 256>>>(0, n);
    k_gemm_mma<<<gemm_grid, 256>>>(b1, nullptr, 0, n);

    // layer 2
    k_agg<<<agg_grid, 256>>>(1, n);
    k_gemm_mma<<<gemm_grid, 256>>>(b2, out, 1, n);

    cudaEventDestroy(evFork);
    cudaEventDestroy(evJoin);
    cudaStreamDestroy(s1);
}